// round 2
// baseline (speedup 1.0000x reference)
#include <cuda_runtime.h>
#include <cuda_bf16.h>
#include <cstdint>

// Problem constants (fixed by the reference implementation).
#define N_NODES  20000
#define N_EDGES  320000
#define NUM_RELS 16
#define IN_FEAT  256
#define OUT_FEAT 256

// Scratch: transformed features T[r][n][o] = (h @ W[r])[n][o]
// 16 * 20000 * 256 floats = 327.68 MB, static device global (alloc-guard safe).
__device__ float g_T[(size_t)NUM_RELS * N_NODES * OUT_FEAT];

// ---------------------------------------------------------------------------
// Kernel 1: per-relation SGEMM  T[r] = h[20000,256] @ W[r][256,256]
// Tiles: BM=128, BN=128, BK=16. 256 threads, 8x8 micro-tile per thread.
// ---------------------------------------------------------------------------
#define BM 128
#define BN 128
#define BK 16
#define TM 8
#define TN 8
#define PAD_A 4  // pad As rows to kill STS bank conflicts

__global__ __launch_bounds__(256, 2)
void rgcn_gemm_kernel(const float* __restrict__ h,
                      const float* __restrict__ W)
{
    const int rel = blockIdx.z;
    const int m0  = blockIdx.y * BM;
    const int n0  = blockIdx.x * BN;

    const float* A = h;                                   // [N_NODES, IN_FEAT]
    const float* B = W + (size_t)rel * IN_FEAT * OUT_FEAT; // [IN_FEAT, OUT_FEAT]
    float*       C = g_T + (size_t)rel * N_NODES * OUT_FEAT;

    __shared__ float As[BK][BM + PAD_A]; // transposed A tile: As[k][m]
    __shared__ float Bs[BK][BN];         // Bs[k][n]

    const int tid = threadIdx.x;   // 0..255
    const int tn  = tid & 15;      // 0..15 -> column group (8 cols each)
    const int tm  = tid >> 4;      // 0..15 -> row group (8 rows each)

    float acc[TM][TN];
    #pragma unroll
    for (int i = 0; i < TM; i++)
        #pragma unroll
        for (int j = 0; j < TN; j++)
            acc[i][j] = 0.0f;

    for (int k0 = 0; k0 < IN_FEAT; k0 += BK) {
        // ---- load A tile: 128 rows x 16 cols = 512 float4, 2 per thread ----
        #pragma unroll
        for (int i = 0; i < 2; i++) {
            int id = tid + i * 256;       // 0..511
            int r  = id >> 2;             // 0..127
            int c  = (id & 3) * 4;        // 0,4,8,12
            int grow = m0 + r;
            float4 v = make_float4(0.f, 0.f, 0.f, 0.f);
            if (grow < N_NODES)
                v = *(const float4*)(A + (size_t)grow * IN_FEAT + k0 + c);
            As[c + 0][r] = v.x;
            As[c + 1][r] = v.y;
            As[c + 2][r] = v.z;
            As[c + 3][r] = v.w;
        }
        // ---- load B tile: 16 rows x 128 cols = 512 float4, 2 per thread ----
        #pragma unroll
        for (int i = 0; i < 2; i++) {
            int id = tid + i * 256;       // 0..511
            int kk = id >> 5;             // 0..15
            int c  = (id & 31) * 4;       // 0..124
            float4 v = *(const float4*)(B + (size_t)(k0 + kk) * OUT_FEAT + n0 + c);
            *(float4*)(&Bs[kk][c]) = v;
        }
        __syncthreads();

        // ---- compute ----
        #pragma unroll
        for (int kk = 0; kk < BK; kk++) {
            float a[TM], b[TN];
            *(float4*)(&a[0]) = *(const float4*)(&As[kk][tm * TM + 0]);
            *(float4*)(&a[4]) = *(const float4*)(&As[kk][tm * TM + 4]);
            *(float4*)(&b[0]) = *(const float4*)(&Bs[kk][tn * TN + 0]);
            *(float4*)(&b[4]) = *(const float4*)(&Bs[kk][tn * TN + 4]);
            #pragma unroll
            for (int i = 0; i < TM; i++)
                #pragma unroll
                for (int j = 0; j < TN; j++)
                    acc[i][j] = fmaf(a[i], b[j], acc[i][j]);
        }
        __syncthreads();
    }

    // ---- store 8x8 micro-tile ----
    #pragma unroll
    for (int i = 0; i < TM; i++) {
        int grow = m0 + tm * TM + i;
        if (grow < N_NODES) {
            float* crow = C + (size_t)grow * OUT_FEAT + n0 + tn * TN;
            *(float4*)(crow + 0) = make_float4(acc[i][0], acc[i][1], acc[i][2], acc[i][3]);
            *(float4*)(crow + 4) = make_float4(acc[i][4], acc[i][5], acc[i][6], acc[i][7]);
        }
    }
}

// ---------------------------------------------------------------------------
// Kernel 2: per-edge gather + scale + atomic scatter into out.
// 64 threads per edge (256 floats = 64 float4), 4 edges per 256-thread block.
// ---------------------------------------------------------------------------
__global__ __launch_bounds__(256)
void rgcn_scatter_kernel(const float* __restrict__ norm,
                         const int*   __restrict__ src,
                         const int*   __restrict__ dst,
                         const int*   __restrict__ rel_type,
                         float*       __restrict__ out,
                         int E)
{
    const int e    = blockIdx.x * 4 + (threadIdx.x >> 6);
    const int lane = threadIdx.x & 63;
    if (e >= E) return;

    const int   s = src[e];
    const int   d = dst[e];
    const int   r = rel_type[e];
    const float n = norm[e];

    const float4 v = ((const float4*)(g_T + ((size_t)r * N_NODES + s) * OUT_FEAT))[lane];
    float* orow = out + (size_t)d * OUT_FEAT + lane * 4;
    atomicAdd(orow + 0, v.x * n);
    atomicAdd(orow + 1, v.y * n);
    atomicAdd(orow + 2, v.z * n);
    atomicAdd(orow + 3, v.w * n);
}

// ---------------------------------------------------------------------------
// Launch
// Inputs (metadata order): 0=h [20000,256] f32, 1=weight [16,256,256] f32,
// 2=norm [320000,1] f32, 3=src [320000] i32, 4=dst [320000] i32,
// 5=rel_type [320000] i32. Output: [20000,256] f32.
// ---------------------------------------------------------------------------
extern "C" void kernel_launch(void* const* d_in, const int* in_sizes, int n_in,
                              void* d_out, int out_size)
{
    const float* h        = (const float*)d_in[0];
    const float* weight   = (const float*)d_in[1];
    const float* norm     = (const float*)d_in[2];
    const int*   src      = (const int*)d_in[3];
    const int*   dst      = (const int*)d_in[4];
    const int*   rel_type = (const int*)d_in[5];
    float*       out      = (float*)d_out;

    const int E = in_sizes[2];  // 320000

    // Zero the (poisoned) output accumulator.
    cudaMemsetAsync(d_out, 0, (size_t)out_size * sizeof(float), 0);

    // K1: T[r] = h @ W[r]
    dim3 grid_g(OUT_FEAT / BN, (N_NODES + BM - 1) / BM, NUM_RELS); // (2, 157, 16)
    rgcn_gemm_kernel<<<grid_g, 256>>>(h, weight);

    // K2: gather + scale + scatter
    int blocks = (E + 3) / 4;
    rgcn_scatter_kernel<<<blocks, 256>>>(norm, src, dst, rel_type, out, E);
}

// round 5
// speedup vs baseline: 2.0400x; 2.0400x over previous
#include <cuda_runtime.h>
#include <cuda_bf16.h>
#include <cstdint>

// ---------------------------------------------------------------------------
// Problem constants
// ---------------------------------------------------------------------------
#define N_NODES  20000
#define N_EDGES  320000
#define NUM_RELS 16
#define IN_FEAT  256
#define OUT_FEAT 256

// ---------------------------------------------------------------------------
// Device scratch (static globals: allocation-guard safe)
// ---------------------------------------------------------------------------
__device__ float g_T[(size_t)NUM_RELS * N_NODES * OUT_FEAT];           // 328 MB
__device__ __align__(16) __nv_bfloat16 g_h_hi[(size_t)N_NODES * IN_FEAT];
__device__ __align__(16) __nv_bfloat16 g_h_lo[(size_t)N_NODES * IN_FEAT];
__device__ __align__(16) __nv_bfloat16 g_wt_hi[(size_t)NUM_RELS * OUT_FEAT * IN_FEAT]; // [r][n][k]
__device__ __align__(16) __nv_bfloat16 g_wt_lo[(size_t)NUM_RELS * OUT_FEAT * IN_FEAT];

// ---------------------------------------------------------------------------
// PTX helpers (arch-agnostic: ldmatrix / mma.sync / cp.async only)
// ---------------------------------------------------------------------------
__device__ __forceinline__ uint32_t smem_u32(const void* p) {
    uint32_t a;
    asm("{ .reg .u64 t; cvta.to.shared.u64 t, %1; cvt.u32.u64 %0, t; }" : "=r"(a) : "l"(p));
    return a;
}

#define LDSM_X4(r, addr) \
    asm volatile("ldmatrix.sync.aligned.m8n8.x4.shared.b16 {%0,%1,%2,%3}, [%4];" \
        : "=r"((r)[0]), "=r"((r)[1]), "=r"((r)[2]), "=r"((r)[3]) : "r"(addr))

#define MMA_BF16(d, a, b0, b1) \
    asm volatile("mma.sync.aligned.m16n8k16.row.col.f32.bf16.bf16.f32 " \
        "{%0,%1,%2,%3}, {%4,%5,%6,%7}, {%8,%9}, {%0,%1,%2,%3};" \
        : "+f"((d)[0]), "+f"((d)[1]), "+f"((d)[2]), "+f"((d)[3]) \
        : "r"((a)[0]), "r"((a)[1]), "r"((a)[2]), "r"((a)[3]), "r"(b0), "r"(b1))

#define CP_ASYNC16(saddr, gptr, nbytes) \
    asm volatile("cp.async.cg.shared.global [%0], [%1], 16, %2;" \
        :: "r"(saddr), "l"(gptr), "r"(nbytes))
#define CP_COMMIT() asm volatile("cp.async.commit_group;" ::: "memory")
#define CP_WAIT(n)  asm volatile("cp.async.wait_group %0;" :: "n"(n) : "memory")

// ---------------------------------------------------------------------------
// Kernel A: split h into bf16 hi/lo
// ---------------------------------------------------------------------------
__global__ void split_h_kernel(const float* __restrict__ h)
{
    int i = blockIdx.x * 256 + threadIdx.x;
    if (i < N_NODES * IN_FEAT) {
        float x = h[i];
        __nv_bfloat16 a = __float2bfloat16(x);
        g_h_hi[i] = a;
        g_h_lo[i] = __float2bfloat16(x - __bfloat162float(a));
    }
}

// ---------------------------------------------------------------------------
// Kernel B: transpose + split W:  Wt[r][n][k] = W[r][k][n], bf16 hi/lo
// grid (8, 8, 16), block (32, 32)
// ---------------------------------------------------------------------------
__global__ void split_wt_kernel(const float* __restrict__ W)
{
    __shared__ float tile[32][33];
    int r  = blockIdx.z;
    int k0 = blockIdx.x * 32;
    int n0 = blockIdx.y * 32;
    tile[threadIdx.y][threadIdx.x] =
        W[(size_t)r * 65536 + (size_t)(k0 + threadIdx.y) * 256 + n0 + threadIdx.x];
    __syncthreads();
    float x = tile[threadIdx.x][threadIdx.y];   // = W[r][k0+tx][n0+ty]
    size_t oi = (size_t)r * 65536 + (size_t)(n0 + threadIdx.y) * 256 + k0 + threadIdx.x;
    __nv_bfloat16 a = __float2bfloat16(x);
    g_wt_hi[oi] = a;
    g_wt_lo[oi] = __float2bfloat16(x - __bfloat162float(a));
}

// ---------------------------------------------------------------------------
// Kernel C: HMMA GEMM.  T[r] = h @ W[r] via bf16 3-term split, fp32 accum.
// CTA 128x128, 8 warps (2m x 4n), warp tile 64x32, mma.m16n8k16.
// Double-buffered cp.async, BK=32 (8 chunks of K=256).
// ---------------------------------------------------------------------------
#define BM 128
#define BN 128
#define BKC 32
#define NCHUNK (IN_FEAT / BKC)     // 8
#define A_STRIDE 80                // 64B payload + 16B pad (conflict-free ldmatrix)
#define TILE_BYTES (128 * A_STRIDE) // 10240 per tile
#define OFF_AHI 0
#define OFF_ALO (1 * TILE_BYTES)
#define OFF_BHI (2 * TILE_BYTES)
#define OFF_BLO (3 * TILE_BYTES)
#define BUF_BYTES (4 * TILE_BYTES)  // 40960
#define SM_TOTAL (2 * BUF_BYTES)    // 81920

#define M_TILES ((N_NODES + BM - 1) / BM)   // 157

__device__ __forceinline__ void load_chunk(
    uint32_t sbuf, int m0, int n0, int k0, int tid,
    const __nv_bfloat16* __restrict__ Ahi, const __nv_bfloat16* __restrict__ Alo,
    const __nv_bfloat16* __restrict__ Bhi, const __nv_bfloat16* __restrict__ Blo)
{
    // Each tile: 128 rows x 64B = 512 x 16B segments; 256 threads -> 2 each.
    #pragma unroll
    for (int it = 0; it < 2; it++) {
        int seg = tid + it * 256;      // 0..511
        int row = seg >> 2;            // 0..127
        int q   = seg & 3;             // 0..3 (16B units)
        uint32_t so = (uint32_t)(row * A_STRIDE + q * 16);
        int grow = m0 + row;
        int okA  = (grow < N_NODES) ? 16 : 0;
        int garow = (grow < N_NODES) ? grow : 0;
        size_t gia = (size_t)garow * IN_FEAT + k0 + q * 8;
        CP_ASYNC16(sbuf + OFF_AHI + so, Ahi + gia, okA);
        CP_ASYNC16(sbuf + OFF_ALO + so, Alo + gia, okA);
        size_t gib = (size_t)(n0 + row) * IN_FEAT + k0 + q * 8;
        CP_ASYNC16(sbuf + OFF_BHI + so, Bhi + gib, 16);
        CP_ASYNC16(sbuf + OFF_BLO + so, Blo + gib, 16);
    }
}

__global__ __launch_bounds__(256)
void rgcn_gemm_hmma_kernel()
{
    extern __shared__ char smem[];
    const uint32_t smem_base = smem_u32(smem);
    const int tid  = threadIdx.x;
    const int wid  = tid >> 5;
    const int lane = tid & 31;
    const int wm   = wid >> 2;   // 0..1  (m warp)
    const int wn   = wid & 3;    // 0..3  (n warp)

    const int m0  = blockIdx.x * BM;
    const int n0  = blockIdx.y * BN;
    const int rel = blockIdx.z;

    const __nv_bfloat16* Ahi = g_h_hi;
    const __nv_bfloat16* Alo = g_h_lo;
    const __nv_bfloat16* Bhi = g_wt_hi + (size_t)rel * OUT_FEAT * IN_FEAT;
    const __nv_bfloat16* Blo = g_wt_lo + (size_t)rel * OUT_FEAT * IN_FEAT;

    float acc[4][4][4];
    #pragma unroll
    for (int i = 0; i < 4; i++)
        #pragma unroll
        for (int j = 0; j < 4; j++)
            #pragma unroll
            for (int k = 0; k < 4; k++)
                acc[i][j][k] = 0.0f;

    // Per-thread ldmatrix base offsets (non-trans x4 address pattern).
    // A (16x16 frag): row = base + (lane&15), k-half = lane>>4
    const uint32_t aoff = (uint32_t)((wm * 64 + (lane & 15)) * A_STRIDE + (lane >> 4) * 16);
    // B (16k x 16n = two n-frags): n = base + ((lane>>4)<<3) + (lane&7), k-half = (lane>>3)&1
    const uint32_t boff = (uint32_t)((wn * 32 + ((lane >> 4) << 3) + (lane & 7)) * A_STRIDE +
                                     ((lane >> 3) & 1) * 16);

    const uint32_t sb[2] = { smem_base, smem_base + BUF_BYTES };

    load_chunk(sb[0], m0, n0, 0, tid, Ahi, Alo, Bhi, Blo);
    CP_COMMIT();

    for (int c = 0; c < NCHUNK; c++) {
        if (c + 1 < NCHUNK) {
            load_chunk(sb[(c + 1) & 1], m0, n0, (c + 1) * BKC, tid, Ahi, Alo, Bhi, Blo);
            CP_COMMIT();
            CP_WAIT(1);
        } else {
            CP_WAIT(0);
        }
        __syncthreads();

        const uint32_t buf = sb[c & 1];
        #pragma unroll
        for (int s = 0; s < 2; s++) {          // two k16 steps per 32-chunk
            uint32_t Ah[4][4], Al[4][4], Bh[2][4], Bl[2][4];
            #pragma unroll
            for (int mi = 0; mi < 4; mi++) {
                uint32_t ad = buf + aoff + (uint32_t)(mi * 16 * A_STRIDE + s * 32);
                LDSM_X4(Ah[mi], ad + OFF_AHI);
                LDSM_X4(Al[mi], ad + OFF_ALO);
            }
            #pragma unroll
            for (int nj = 0; nj < 2; nj++) {
                uint32_t bd = buf + boff + (uint32_t)(nj * 16 * A_STRIDE + s * 32);
                LDSM_X4(Bh[nj], bd + OFF_BHI);
                LDSM_X4(Bl[nj], bd + OFF_BLO);
            }
            #pragma unroll
            for (int mi = 0; mi < 4; mi++) {
                #pragma unroll
                for (int nf = 0; nf < 4; nf++) {
                    const int nj = nf >> 1, p = (nf & 1) * 2;
                    MMA_BF16(acc[mi][nf], Ah[mi], Bh[nj][p], Bh[nj][p + 1]);
                    MMA_BF16(acc[mi][nf], Ah[mi], Bl[nj][p], Bl[nj][p + 1]);
                    MMA_BF16(acc[mi][nf], Al[mi], Bh[nj][p], Bh[nj][p + 1]);
                }
            }
        }
        __syncthreads();
    }

    // Epilogue: c0,c1 at (row g, col tg*2), c2,c3 at (row g+8).
    const int g  = lane >> 2;
    const int tg = lane & 3;
    float* C = g_T + (size_t)rel * N_NODES * OUT_FEAT;
    #pragma unroll
    for (int mi = 0; mi < 4; mi++) {
        const int row0 = m0 + wm * 64 + mi * 16 + g;
        #pragma unroll
        for (int nf = 0; nf < 4; nf++) {
            const int col = n0 + wn * 32 + nf * 8 + tg * 2;
            if (row0 < N_NODES)
                *(float2*)(C + (size_t)row0 * OUT_FEAT + col) =
                    make_float2(acc[mi][nf][0], acc[mi][nf][1]);
            if (row0 + 8 < N_NODES)
                *(float2*)(C + (size_t)(row0 + 8) * OUT_FEAT + col) =
                    make_float2(acc[mi][nf][2], acc[mi][nf][3]);
        }
    }
}

// ---------------------------------------------------------------------------
// Kernel D: per-edge gather + scale + atomic scatter
// ---------------------------------------------------------------------------
__global__ __launch_bounds__(256)
void rgcn_scatter_kernel(const float* __restrict__ norm,
                         const int*   __restrict__ src,
                         const int*   __restrict__ dst,
                         const int*   __restrict__ rel_type,
                         float*       __restrict__ out,
                         int E)
{
    const int e    = blockIdx.x * 4 + (threadIdx.x >> 6);
    const int lane = threadIdx.x & 63;
    if (e >= E) return;

    const int   s = src[e];
    const int   d = dst[e];
    const int   r = rel_type[e];
    const float n = norm[e];

    const float4 v = ((const float4*)(g_T + ((size_t)r * N_NODES + s) * OUT_FEAT))[lane];
    float* orow = out + (size_t)d * OUT_FEAT + lane * 4;
    atomicAdd(orow + 0, v.x * n);
    atomicAdd(orow + 1, v.y * n);
    atomicAdd(orow + 2, v.z * n);
    atomicAdd(orow + 3, v.w * n);
}

// ---------------------------------------------------------------------------
// Launch
// ---------------------------------------------------------------------------
extern "C" void kernel_launch(void* const* d_in, const int* in_sizes, int n_in,
                              void* d_out, int out_size)
{
    const float* h        = (const float*)d_in[0];
    const float* weight   = (const float*)d_in[1];
    const float* norm     = (const float*)d_in[2];
    const int*   src      = (const int*)d_in[3];
    const int*   dst      = (const int*)d_in[4];
    const int*   rel_type = (const int*)d_in[5];
    float*       out      = (float*)d_out;

    const int E = in_sizes[2];  // 320000

    cudaMemsetAsync(d_out, 0, (size_t)out_size * sizeof(float), 0);

    split_h_kernel<<<(N_NODES * IN_FEAT + 255) / 256, 256>>>(h);
    split_wt_kernel<<<dim3(8, 8, NUM_RELS), dim3(32, 32)>>>(weight);

    cudaFuncSetAttribute(rgcn_gemm_hmma_kernel,
                         cudaFuncAttributeMaxDynamicSharedMemorySize, SM_TOTAL);
    rgcn_gemm_hmma_kernel<<<dim3(M_TILES, OUT_FEAT / BN, NUM_RELS), 256, SM_TOTAL>>>();

    rgcn_scatter_kernel<<<(E + 3) / 4, 256>>>(norm, src, dst, rel_type, out, E);
}

// round 6
// speedup vs baseline: 2.4932x; 1.2221x over previous
#include <cuda_runtime.h>
#include <cuda_bf16.h>
#include <cstdint>

// ---------------------------------------------------------------------------
// Problem constants
// ---------------------------------------------------------------------------
#define N_NODES  20000
#define N_EDGES  320000
#define NUM_RELS 16
#define IN_FEAT  256
#define OUT_FEAT 256

// ---------------------------------------------------------------------------
// Device scratch (static globals: allocation-guard safe)
// ---------------------------------------------------------------------------
__device__ float g_T[(size_t)NUM_RELS * N_NODES * OUT_FEAT];           // 328 MB
__device__ __align__(16) __nv_bfloat16 g_h_hi[(size_t)N_NODES * IN_FEAT];
__device__ __align__(16) __nv_bfloat16 g_h_lo[(size_t)N_NODES * IN_FEAT];
__device__ __align__(16) __nv_bfloat16 g_wt_hi[(size_t)NUM_RELS * OUT_FEAT * IN_FEAT]; // [r][n][k]
__device__ __align__(16) __nv_bfloat16 g_wt_lo[(size_t)NUM_RELS * OUT_FEAT * IN_FEAT];

// CSR-by-dst scratch
__device__ int  g_cnt[N_NODES];
__device__ int  g_fill[N_NODES];
__device__ int  g_row[N_NODES + 1];
__device__ int2 g_es[N_EDGES];   // {src | (rel<<16), bitcast(norm)} sorted by dst

// ---------------------------------------------------------------------------
// PTX helpers (arch-agnostic: ldmatrix / mma.sync / cp.async only)
// ---------------------------------------------------------------------------
__device__ __forceinline__ uint32_t smem_u32(const void* p) {
    uint32_t a;
    asm("{ .reg .u64 t; cvta.to.shared.u64 t, %1; cvt.u32.u64 %0, t; }" : "=r"(a) : "l"(p));
    return a;
}

#define LDSM_X4(r, addr) \
    asm volatile("ldmatrix.sync.aligned.m8n8.x4.shared.b16 {%0,%1,%2,%3}, [%4];" \
        : "=r"((r)[0]), "=r"((r)[1]), "=r"((r)[2]), "=r"((r)[3]) : "r"(addr))

#define MMA_BF16(d, a, b0, b1) \
    asm volatile("mma.sync.aligned.m16n8k16.row.col.f32.bf16.bf16.f32 " \
        "{%0,%1,%2,%3}, {%4,%5,%6,%7}, {%8,%9}, {%0,%1,%2,%3};" \
        : "+f"((d)[0]), "+f"((d)[1]), "+f"((d)[2]), "+f"((d)[3]) \
        : "r"((a)[0]), "r"((a)[1]), "r"((a)[2]), "r"((a)[3]), "r"(b0), "r"(b1))

#define CP_ASYNC16(saddr, gptr, nbytes) \
    asm volatile("cp.async.cg.shared.global [%0], [%1], 16, %2;" \
        :: "r"(saddr), "l"(gptr), "r"(nbytes))
#define CP_COMMIT() asm volatile("cp.async.commit_group;" ::: "memory")
#define CP_WAIT(n)  asm volatile("cp.async.wait_group %0;" :: "n"(n) : "memory")

// ---------------------------------------------------------------------------
// Kernel A: split h into bf16 hi/lo
// ---------------------------------------------------------------------------
__global__ void split_h_kernel(const float* __restrict__ h)
{
    int i = blockIdx.x * 256 + threadIdx.x;
    if (i < N_NODES * IN_FEAT) {
        float x = h[i];
        __nv_bfloat16 a = __float2bfloat16(x);
        g_h_hi[i] = a;
        g_h_lo[i] = __float2bfloat16(x - __bfloat162float(a));
    }
}

// ---------------------------------------------------------------------------
// Kernel B: transpose + split W:  Wt[r][n][k] = W[r][k][n], bf16 hi/lo
// ---------------------------------------------------------------------------
__global__ void split_wt_kernel(const float* __restrict__ W)
{
    __shared__ float tile[32][33];
    int r  = blockIdx.z;
    int k0 = blockIdx.x * 32;
    int n0 = blockIdx.y * 32;
    tile[threadIdx.y][threadIdx.x] =
        W[(size_t)r * 65536 + (size_t)(k0 + threadIdx.y) * 256 + n0 + threadIdx.x];
    __syncthreads();
    float x = tile[threadIdx.x][threadIdx.y];   // = W[r][k0+tx][n0+ty]
    size_t oi = (size_t)r * 65536 + (size_t)(n0 + threadIdx.y) * 256 + k0 + threadIdx.x;
    __nv_bfloat16 a = __float2bfloat16(x);
    g_wt_hi[oi] = a;
    g_wt_lo[oi] = __float2bfloat16(x - __bfloat162float(a));
}

// ---------------------------------------------------------------------------
// CSR build kernels
// ---------------------------------------------------------------------------
__global__ void csr_zero_kernel()
{
    int i = blockIdx.x * 256 + threadIdx.x;
    if (i < N_NODES) { g_cnt[i] = 0; g_fill[i] = 0; }
}

__global__ void csr_hist_kernel(const int* __restrict__ dst, int E)
{
    int e = blockIdx.x * 256 + threadIdx.x;
    if (e < E) atomicAdd(&g_cnt[dst[e]], 1);
}

// Single-block exclusive scan of g_cnt -> g_row (plus total at g_row[N]).
__global__ void csr_scan_kernel()
{
    __shared__ int ssum[256];
    const int t  = threadIdx.x;
    const int CH = (N_NODES + 255) / 256;   // 79
    const int base = t * CH;

    int s = 0;
    for (int i = 0; i < CH; i++) {
        int idx = base + i;
        if (idx < N_NODES) s += g_cnt[idx];
    }
    ssum[t] = s;
    __syncthreads();
    // Hillis-Steele inclusive scan over 256 chunk sums
    for (int off = 1; off < 256; off <<= 1) {
        int v = (t >= off) ? ssum[t - off] : 0;
        __syncthreads();
        ssum[t] += v;
        __syncthreads();
    }
    int run = (t > 0) ? ssum[t - 1] : 0;
    for (int i = 0; i < CH; i++) {
        int idx = base + i;
        if (idx < N_NODES) { g_row[idx] = run; run += g_cnt[idx]; }
    }
    if (t == 255) g_row[N_NODES] = run;
}

__global__ void csr_fill_kernel(const int* __restrict__ src,
                                const int* __restrict__ dst,
                                const int* __restrict__ rel_type,
                                const float* __restrict__ norm, int E)
{
    int e = blockIdx.x * 256 + threadIdx.x;
    if (e < E) {
        int d = dst[e];
        int pos = g_row[d] + atomicAdd(&g_fill[d], 1);
        g_es[pos] = make_int2(src[e] | (rel_type[e] << 16), __float_as_int(norm[e]));
    }
}

// ---------------------------------------------------------------------------
// Kernel C: HMMA GEMM.  T[r] = h @ W[r] via bf16 3-term split, fp32 accum.
// CTA 128x128, 8 warps (2m x 4n), warp tile 64x32, mma.m16n8k16.
// Double-buffered cp.async, BK=32 (8 chunks of K=256).
// ---------------------------------------------------------------------------
#define BM 128
#define BN 128
#define BKC 32
#define NCHUNK (IN_FEAT / BKC)      // 8
#define A_STRIDE 80                 // 64B payload + 16B pad
#define TILE_BYTES (128 * A_STRIDE) // 10240 per tile
#define OFF_AHI 0
#define OFF_ALO (1 * TILE_BYTES)
#define OFF_BHI (2 * TILE_BYTES)
#define OFF_BLO (3 * TILE_BYTES)
#define BUF_BYTES (4 * TILE_BYTES)  // 40960
#define SM_TOTAL (2 * BUF_BYTES)    // 81920

#define M_TILES ((N_NODES + BM - 1) / BM)   // 157

__device__ __forceinline__ void load_chunk(
    uint32_t sbuf, int m0, int n0, int k0, int tid,
    const __nv_bfloat16* __restrict__ Ahi, const __nv_bfloat16* __restrict__ Alo,
    const __nv_bfloat16* __restrict__ Bhi, const __nv_bfloat16* __restrict__ Blo)
{
    #pragma unroll
    for (int it = 0; it < 2; it++) {
        int seg = tid + it * 256;      // 0..511
        int row = seg >> 2;            // 0..127
        int q   = seg & 3;             // 0..3 (16B units)
        uint32_t so = (uint32_t)(row * A_STRIDE + q * 16);
        int grow = m0 + row;
        int okA  = (grow < N_NODES) ? 16 : 0;
        int garow = (grow < N_NODES) ? grow : 0;
        size_t gia = (size_t)garow * IN_FEAT + k0 + q * 8;
        CP_ASYNC16(sbuf + OFF_AHI + so, Ahi + gia, okA);
        CP_ASYNC16(sbuf + OFF_ALO + so, Alo + gia, okA);
        size_t gib = (size_t)(n0 + row) * IN_FEAT + k0 + q * 8;
        CP_ASYNC16(sbuf + OFF_BHI + so, Bhi + gib, 16);
        CP_ASYNC16(sbuf + OFF_BLO + so, Blo + gib, 16);
    }
}

__global__ __launch_bounds__(256)
void rgcn_gemm_hmma_kernel()
{
    extern __shared__ char smem[];
    const uint32_t smem_base = smem_u32(smem);
    const int tid  = threadIdx.x;
    const int wid  = tid >> 5;
    const int lane = tid & 31;
    const int wm   = wid >> 2;
    const int wn   = wid & 3;

    const int m0  = blockIdx.x * BM;
    const int n0  = blockIdx.y * BN;
    const int rel = blockIdx.z;

    const __nv_bfloat16* Ahi = g_h_hi;
    const __nv_bfloat16* Alo = g_h_lo;
    const __nv_bfloat16* Bhi = g_wt_hi + (size_t)rel * OUT_FEAT * IN_FEAT;
    const __nv_bfloat16* Blo = g_wt_lo + (size_t)rel * OUT_FEAT * IN_FEAT;

    float acc[4][4][4];
    #pragma unroll
    for (int i = 0; i < 4; i++)
        #pragma unroll
        for (int j = 0; j < 4; j++)
            #pragma unroll
            for (int k = 0; k < 4; k++)
                acc[i][j][k] = 0.0f;

    const uint32_t aoff = (uint32_t)((wm * 64 + (lane & 15)) * A_STRIDE + (lane >> 4) * 16);
    const uint32_t boff = (uint32_t)((wn * 32 + ((lane >> 4) << 3) + (lane & 7)) * A_STRIDE +
                                     ((lane >> 3) & 1) * 16);

    const uint32_t sb[2] = { smem_base, smem_base + BUF_BYTES };

    load_chunk(sb[0], m0, n0, 0, tid, Ahi, Alo, Bhi, Blo);
    CP_COMMIT();

    for (int c = 0; c < NCHUNK; c++) {
        if (c + 1 < NCHUNK) {
            load_chunk(sb[(c + 1) & 1], m0, n0, (c + 1) * BKC, tid, Ahi, Alo, Bhi, Blo);
            CP_COMMIT();
            CP_WAIT(1);
        } else {
            CP_WAIT(0);
        }
        __syncthreads();

        const uint32_t buf = sb[c & 1];
        #pragma unroll
        for (int s = 0; s < 2; s++) {
            uint32_t Ah[4][4], Al[4][4], Bh[2][4], Bl[2][4];
            #pragma unroll
            for (int mi = 0; mi < 4; mi++) {
                uint32_t ad = buf + aoff + (uint32_t)(mi * 16 * A_STRIDE + s * 32);
                LDSM_X4(Ah[mi], ad + OFF_AHI);
                LDSM_X4(Al[mi], ad + OFF_ALO);
            }
            #pragma unroll
            for (int nj = 0; nj < 2; nj++) {
                uint32_t bd = buf + boff + (uint32_t)(nj * 16 * A_STRIDE + s * 32);
                LDSM_X4(Bh[nj], bd + OFF_BHI);
                LDSM_X4(Bl[nj], bd + OFF_BLO);
            }
            #pragma unroll
            for (int mi = 0; mi < 4; mi++) {
                #pragma unroll
                for (int nf = 0; nf < 4; nf++) {
                    const int nj = nf >> 1, p = (nf & 1) * 2;
                    MMA_BF16(acc[mi][nf], Ah[mi], Bh[nj][p], Bh[nj][p + 1]);
                    MMA_BF16(acc[mi][nf], Ah[mi], Bl[nj][p], Bl[nj][p + 1]);
                    MMA_BF16(acc[mi][nf], Al[mi], Bh[nj][p], Bh[nj][p + 1]);
                }
            }
        }
        __syncthreads();
    }

    const int g  = lane >> 2;
    const int tg = lane & 3;
    float* C = g_T + (size_t)rel * N_NODES * OUT_FEAT;
    #pragma unroll
    for (int mi = 0; mi < 4; mi++) {
        const int row0 = m0 + wm * 64 + mi * 16 + g;
        #pragma unroll
        for (int nf = 0; nf < 4; nf++) {
            const int col = n0 + wn * 32 + nf * 8 + tg * 2;
            if (row0 < N_NODES)
                *(float2*)(C + (size_t)row0 * OUT_FEAT + col) =
                    make_float2(acc[mi][nf][0], acc[mi][nf][1]);
            if (row0 + 8 < N_NODES)
                *(float2*)(C + (size_t)(row0 + 8) * OUT_FEAT + col) =
                    make_float2(acc[mi][nf][2], acc[mi][nf][3]);
        }
    }
}

// ---------------------------------------------------------------------------
// Kernel D: atomic-free gather.  64 threads per dst node (4 floats each),
// 4 nodes per 256-thread block.  acc in registers, single coalesced store.
// ---------------------------------------------------------------------------
__global__ __launch_bounds__(256)
void rgcn_gather_kernel(float* __restrict__ out)
{
    const int node = blockIdx.x * 4 + (threadIdx.x >> 6);
    const int lane = threadIdx.x & 63;
    if (node >= N_NODES) return;

    const int beg = g_row[node];
    const int end = g_row[node + 1];

    float4 acc = make_float4(0.f, 0.f, 0.f, 0.f);
    int i = beg;
    // 2-way unroll for MLP
    for (; i + 1 < end; i += 2) {
        int2 e0 = g_es[i];
        int2 e1 = g_es[i + 1];
        int   s0 = e0.x & 0xFFFF, r0 = e0.x >> 16;
        int   s1 = e1.x & 0xFFFF, r1 = e1.x >> 16;
        float n0 = __int_as_float(e0.y);
        float n1 = __int_as_float(e1.y);
        float4 v0 = ((const float4*)(g_T + ((size_t)r0 * N_NODES + s0) * OUT_FEAT))[lane];
        float4 v1 = ((const float4*)(g_T + ((size_t)r1 * N_NODES + s1) * OUT_FEAT))[lane];
        acc.x = fmaf(v0.x, n0, acc.x); acc.y = fmaf(v0.y, n0, acc.y);
        acc.z = fmaf(v0.z, n0, acc.z); acc.w = fmaf(v0.w, n0, acc.w);
        acc.x = fmaf(v1.x, n1, acc.x); acc.y = fmaf(v1.y, n1, acc.y);
        acc.z = fmaf(v1.z, n1, acc.z); acc.w = fmaf(v1.w, n1, acc.w);
    }
    if (i < end) {
        int2 e0 = g_es[i];
        int   s0 = e0.x & 0xFFFF, r0 = e0.x >> 16;
        float n0 = __int_as_float(e0.y);
        float4 v0 = ((const float4*)(g_T + ((size_t)r0 * N_NODES + s0) * OUT_FEAT))[lane];
        acc.x = fmaf(v0.x, n0, acc.x); acc.y = fmaf(v0.y, n0, acc.y);
        acc.z = fmaf(v0.z, n0, acc.z); acc.w = fmaf(v0.w, n0, acc.w);
    }

    ((float4*)(out + (size_t)node * OUT_FEAT))[lane] = acc;
}

// ---------------------------------------------------------------------------
// Launch
// ---------------------------------------------------------------------------
extern "C" void kernel_launch(void* const* d_in, const int* in_sizes, int n_in,
                              void* d_out, int out_size)
{
    const float* h        = (const float*)d_in[0];
    const float* weight   = (const float*)d_in[1];
    const float* norm     = (const float*)d_in[2];
    const int*   src      = (const int*)d_in[3];
    const int*   dst      = (const int*)d_in[4];
    const int*   rel_type = (const int*)d_in[5];
    float*       out      = (float*)d_out;

    const int E = in_sizes[2];  // 320000

    // Split/transpose precompute
    split_h_kernel<<<(N_NODES * IN_FEAT + 255) / 256, 256>>>(h);
    split_wt_kernel<<<dim3(8, 8, NUM_RELS), dim3(32, 32)>>>(weight);

    // CSR-by-dst build (independent of GEMM)
    csr_zero_kernel<<<(N_NODES + 255) / 256, 256>>>();
    csr_hist_kernel<<<(E + 255) / 256, 256>>>(dst, E);
    csr_scan_kernel<<<1, 256>>>();
    csr_fill_kernel<<<(E + 255) / 256, 256>>>(src, dst, rel_type, norm, E);

    // Tensor-core (HMMA) GEMM: T[r] = h @ W[r]
    cudaFuncSetAttribute(rgcn_gemm_hmma_kernel,
                         cudaFuncAttributeMaxDynamicSharedMemorySize, SM_TOTAL);
    rgcn_gemm_hmma_kernel<<<dim3(M_TILES, OUT_FEAT / BN, NUM_RELS), 256, SM_TOTAL>>>();

    // Atomic-free gather (writes every output row; no memset needed)
    rgcn_gather_kernel<<<(N_NODES + 3) / 4, 256>>>(out);
}